// round 5
// baseline (speedup 1.0000x reference)
#include <cuda_runtime.h>
#include <mma.h>
#include <math.h>

using namespace nvcuda;

// Problem constants (fixed shapes for this problem)
#define T_TOK 4096           // B*S tokens
#define DDIM  1024           // embed dim
#define UDIM  4096           // hidden dim
#define NEXP  8              // experts
#define NSLOT (T_TOK * 2)    // token-slot = (token<<1)|k, k in {0,1}

// Scratch in device globals (no allocations allowed in kernel_launch)
__device__ float g_h[(size_t)NSLOT * UDIM];   // gelu(up) activations per slot   (134 MB)
__device__ float g_y[(size_t)NSLOT * DDIM];   // weighted down outputs per slot  (33.5 MB)
__device__ float g_w[NSLOT];                  // router weight per slot
__device__ int   g_list[NEXP * T_TOK];        // per-expert slot lists
__device__ int   g_count[NEXP];               // per-expert token counts

// ---------------------------------------------------------------------------
__global__ void init_kernel() {
    if (threadIdx.x < NEXP) g_count[threadIdx.x] = 0;
}

// ---------------------------------------------------------------------------
// Router: one warp per token. Exact fp32 logits, deterministic top-2 with
// lower-index tie-break (matches jax.lax.top_k), softmax over the two logits.
__global__ void router_kernel(const float* __restrict__ x,
                              const float* __restrict__ wr) {
    int gw   = (blockIdx.x * blockDim.x + threadIdx.x) >> 5;
    int lane = threadIdx.x & 31;
    if (gw >= T_TOK) return;

    const float* xr = x + (size_t)gw * DDIM;
    float xv[32];
#pragma unroll
    for (int i = 0; i < 32; i++) xv[i] = xr[lane + 32 * i];

    float lg[NEXP];
#pragma unroll
    for (int e = 0; e < NEXP; e++) {
        const float* w = wr + (size_t)e * DDIM;
        float s = 0.f;
#pragma unroll
        for (int i = 0; i < 32; i++) s = fmaf(xv[i], w[lane + 32 * i], s);
#pragma unroll
        for (int o = 16; o > 0; o >>= 1) s += __shfl_xor_sync(0xffffffffu, s, o);
        lg[e] = s;
    }

    if (lane == 0) {
        int i0 = 0; float v0 = lg[0];
#pragma unroll
        for (int e = 1; e < NEXP; e++) if (lg[e] > v0) { v0 = lg[e]; i0 = e; }
        int i1 = -1; float v1 = -INFINITY;
#pragma unroll
        for (int e = 0; e < NEXP; e++)
            if (e != i0 && lg[e] > v1) { v1 = lg[e]; i1 = e; }

        float e1 = expf(v1 - v0);
        float s  = 1.f + e1;
        float w0 = 1.f / s;
        float w1 = e1 / s;

        int p0 = atomicAdd(&g_count[i0], 1);
        g_list[i0 * T_TOK + p0] = (gw << 1);
        g_w[gw * 2 + 0] = w0;

        int p1 = atomicAdd(&g_count[i1], 1);
        g_list[i1 * T_TOK + p1] = (gw << 1) | 1;
        g_w[gw * 2 + 1] = w1;
    }
}

// ---------------------------------------------------------------------------
// Grouped GEMM, TF32 wmma, 2-stage software pipeline (global->regs prefetch
// overlapped with mma on the other smem buffer).
// C[M_e, NDIM] = A[M_e, KDIM] * W_e[NDIM, KDIM]^T
// IS_UP:   A = x rows gathered by token (slot>>1); epilogue bias + exact GELU -> g_h
// !IS_UP:  A = g_h rows by slot;          epilogue bias, * router weight  -> g_y
#define BM 128
#define BN 64
#define BK 16
#define LDT (BK + 4)   // 20 floats (80 B, 16B-aligned stride)
#define LDC (BN + 4)   // 68 floats (272 B, 16B-aligned stride)
#define BUF_FLOATS (BM * LDT + BN * LDT)   // 3840 floats per pipeline stage

template <int NDIM, int KDIM, bool IS_UP>
__global__ __launch_bounds__(256)
void moe_gemm(const float* __restrict__ A0, const float* __restrict__ Wg,
              const float* __restrict__ bias) {
    // Overlay: two pipeline buffers (2*3840 floats) inside the C-tile region
    // (BM*LDC = 8704 floats). Epilogue reuses from offset 0 after final sync.
    __shared__ float smem[BM * LDC];
    __shared__ int   srow[BM];

    const int e   = blockIdx.z;
    const int cnt = g_count[e];
    const int m0  = blockIdx.y * BM;
    if (m0 >= cnt) return;
    const int n0  = blockIdx.x * BN;
    const int tid = threadIdx.x;

    if (tid < BM) {
        int r = m0 + tid;
        srow[tid] = (r < cnt) ? g_list[e * T_TOK + r] : -1;
    }
    __syncthreads();

    const float* W = Wg + (size_t)e * NDIM * KDIM;

    // ---- loop-invariant gather pointers / smem offsets -------------------
    // A tile: 128 rows x 16 cols = 512 float4; 2 per thread.
    const float* aptr[2];
    int          offA[2];
#pragma unroll
    for (int it = 0; it < 2; it++) {
        int f4 = tid + it * 256;
        int r  = f4 >> 2;
        int c4 = f4 & 3;
        int slot = srow[r];
        aptr[it] = (slot < 0) ? nullptr
                 : (IS_UP ? (A0 + (size_t)(slot >> 1) * KDIM + c4 * 4)
                          : (&g_h[0] + (size_t)slot * KDIM + c4 * 4));
        offA[it] = r * LDT + c4 * 4;
    }
    // B tile: 64 rows x 16 cols = 256 float4; 1 per thread.
    const float* bptr = W + (size_t)(n0 + (tid >> 2)) * KDIM + (tid & 3) * 4;
    const int    offB = BM * LDT + (tid >> 2) * LDT + (tid & 3) * 4;

    float4 ra[2], rbv;
    auto LOAD = [&](int k0) {
#pragma unroll
        for (int it = 0; it < 2; it++)
            ra[it] = aptr[it]
                ? *reinterpret_cast<const float4*>(aptr[it] + k0)
                : make_float4(0.f, 0.f, 0.f, 0.f);
        rbv = *reinterpret_cast<const float4*>(bptr + k0);
    };
    auto STORE = [&](float* base) {
#pragma unroll
        for (int it = 0; it < 2; it++) {
            float* d = base + offA[it];
            d[0] = wmma::__float_to_tf32(ra[it].x);
            d[1] = wmma::__float_to_tf32(ra[it].y);
            d[2] = wmma::__float_to_tf32(ra[it].z);
            d[3] = wmma::__float_to_tf32(ra[it].w);
        }
        float* d = base + offB;
        d[0] = wmma::__float_to_tf32(rbv.x);
        d[1] = wmma::__float_to_tf32(rbv.y);
        d[2] = wmma::__float_to_tf32(rbv.z);
        d[3] = wmma::__float_to_tf32(rbv.w);
    };

    wmma::fragment<wmma::accumulator, 16, 16, 8, float> fc[2][2];
#pragma unroll
    for (int i = 0; i < 2; i++)
#pragma unroll
        for (int j = 0; j < 2; j++) wmma::fill_fragment(fc[i][j], 0.f);

    const int warp = tid >> 5;
    const int wm   = warp & 3;    // 0..3 -> 32-row slab
    const int wn   = warp >> 2;   // 0..1 -> 32-col slab

    float* buf[2] = { smem, smem + BUF_FLOATS };
    constexpr int KT = KDIM / BK;

    // Prologue: fill stage 0
    LOAD(0);
    STORE(buf[0]);
    __syncthreads();

    for (int kt = 0; kt < KT; kt++) {
        const int cur = kt & 1;
        // Prefetch next k-tile into registers (latency covered by mma below)
        if (kt + 1 < KT) LOAD((kt + 1) * BK);

        const float* sA = buf[cur];
        const float* sB = buf[cur] + BM * LDT;
#pragma unroll
        for (int kk = 0; kk < BK; kk += 8) {
            wmma::fragment<wmma::matrix_a, 16, 16, 8, wmma::precision::tf32,
                           wmma::row_major> fa[2];
            wmma::fragment<wmma::matrix_b, 16, 16, 8, wmma::precision::tf32,
                           wmma::col_major> fb[2];
#pragma unroll
            for (int i = 0; i < 2; i++)
                wmma::load_matrix_sync(fa[i], sA + (wm * 32 + i * 16) * LDT + kk, LDT);
#pragma unroll
            for (int j = 0; j < 2; j++)
                wmma::load_matrix_sync(fb[j], sB + (wn * 32 + j * 16) * LDT + kk, LDT);
#pragma unroll
            for (int i = 0; i < 2; i++)
#pragma unroll
                for (int j = 0; j < 2; j++)
                    wmma::mma_sync(fc[i][j], fa[i], fb[j], fc[i][j]);
        }

        // Fill the other stage (safe: it was last consumed before the previous
        // barrier), then one barrier per iteration.
        if (kt + 1 < KT) STORE(buf[(kt + 1) & 1]);
        __syncthreads();
    }

    // Epilogue: park accumulators in smem, then coalesced elementwise pass
#pragma unroll
    for (int i = 0; i < 2; i++)
#pragma unroll
        for (int j = 0; j < 2; j++)
            wmma::store_matrix_sync(smem + (wm * 32 + i * 16) * LDC + wn * 32 + j * 16,
                                    fc[i][j], LDC, wmma::mem_row_major);
    __syncthreads();

    const int c  = tid & (BN - 1);
    const int rb = tid >> 6;   // 0..3
    const float bcol = bias[(size_t)e * NDIM + n0 + c];
#pragma unroll 4
    for (int r = rb; r < BM; r += 4) {
        int slot = srow[r];
        if (slot < 0) continue;
        float v = smem[r * LDC + c] + bcol;
        if (IS_UP) {
            // exact GELU: 0.5*x*(1+erf(x/sqrt(2)))
            v = 0.5f * v * (1.f + erff(v * 0.70710678118654752f));
            g_h[(size_t)slot * UDIM + n0 + c] = v;
        } else {
            g_y[(size_t)slot * DDIM + n0 + c] = v * g_w[slot];
        }
    }
}

// ---------------------------------------------------------------------------
// out[t,d] = y[slot=2t] + y[slot=2t+1]   (fixed order -> deterministic)
__global__ void combine_kernel(float* __restrict__ out) {
    int i = blockIdx.x * blockDim.x + threadIdx.x;
    if (i >= T_TOK * DDIM) return;
    int t = i >> 10;          // DDIM = 1024
    int d = i & (DDIM - 1);
    out[i] = g_y[(size_t)(2 * t) * DDIM + d] +
             g_y[(size_t)(2 * t + 1) * DDIM + d];
}

// ---------------------------------------------------------------------------
extern "C" void kernel_launch(void* const* d_in, const int* in_sizes, int n_in,
                              void* d_out, int out_size) {
    const float* x  = (const float*)d_in[0];
    const float* wr = (const float*)d_in[1];
    const float* wu = (const float*)d_in[2];
    const float* bu = (const float*)d_in[3];
    const float* wd = (const float*)d_in[4];
    const float* bd = (const float*)d_in[5];
    float* out = (float*)d_out;

    init_kernel<<<1, 32>>>();
    router_kernel<<<(T_TOK * 32) / 256, 256>>>(x, wr);

    dim3 gu(UDIM / BN, T_TOK / BM, NEXP);   // (64, 32, 8)
    moe_gemm<UDIM, DDIM, true><<<gu, 256>>>(x, wu, bu);

    dim3 gd(DDIM / BN, T_TOK / BM, NEXP);   // (16, 32, 8)
    moe_gemm<DDIM, UDIM, false><<<gd, 256>>>(x, wd, bd);

    combine_kernel<<<(T_TOK * DDIM + 255) / 256, 256>>>(out);
}

// round 9
// speedup vs baseline: 1.0042x; 1.0042x over previous
#include <cuda_runtime.h>
#include <mma.h>
#include <math.h>
#include <stdint.h>

using namespace nvcuda;

// Problem constants (fixed shapes for this problem)
#define T_TOK 4096           // B*S tokens
#define DDIM  1024           // embed dim
#define UDIM  4096           // hidden dim
#define NEXP  8              // experts
#define NSLOT (T_TOK * 2)    // token-slot = (token<<1)|k, k in {0,1}

// Scratch in device globals (no allocations allowed in kernel_launch)
__device__ float g_h[(size_t)NSLOT * UDIM];   // gelu(up) activations per slot
__device__ float g_y[(size_t)NSLOT * DDIM];   // weighted down outputs per slot
__device__ float g_w[NSLOT];                  // router weight per slot
__device__ int   g_list[NEXP * T_TOK];        // per-expert slot lists
__device__ int   g_count[NEXP];               // per-expert token counts

// ---------------------------------------------------------------------------
__global__ void init_kernel() {
    if (threadIdx.x < NEXP) g_count[threadIdx.x] = 0;
}

// ---------------------------------------------------------------------------
// Router: one warp per token. Exact fp32 logits, deterministic top-2 with
// lower-index tie-break (matches jax.lax.top_k), softmax over the two logits.
__global__ void router_kernel(const float* __restrict__ x,
                              const float* __restrict__ wr) {
    int gw   = (blockIdx.x * blockDim.x + threadIdx.x) >> 5;
    int lane = threadIdx.x & 31;
    if (gw >= T_TOK) return;

    const float* xr = x + (size_t)gw * DDIM;
    float xv[32];
#pragma unroll
    for (int i = 0; i < 32; i++) xv[i] = xr[lane + 32 * i];

    float lg[NEXP];
#pragma unroll
    for (int e = 0; e < NEXP; e++) {
        const float* w = wr + (size_t)e * DDIM;
        float s = 0.f;
#pragma unroll
        for (int i = 0; i < 32; i++) s = fmaf(xv[i], w[lane + 32 * i], s);
#pragma unroll
        for (int o = 16; o > 0; o >>= 1) s += __shfl_xor_sync(0xffffffffu, s, o);
        lg[e] = s;
    }

    if (lane == 0) {
        int i0 = 0; float v0 = lg[0];
#pragma unroll
        for (int e = 1; e < NEXP; e++) if (lg[e] > v0) { v0 = lg[e]; i0 = e; }
        int i1 = -1; float v1 = -INFINITY;
#pragma unroll
        for (int e = 0; e < NEXP; e++)
            if (e != i0 && lg[e] > v1) { v1 = lg[e]; i1 = e; }

        float e1 = expf(v1 - v0);
        float s  = 1.f + e1;

        int p0 = atomicAdd(&g_count[i0], 1);
        g_list[i0 * T_TOK + p0] = (gw << 1);
        g_w[gw * 2 + 0] = 1.f / s;

        int p1 = atomicAdd(&g_count[i1], 1);
        g_list[i1 * T_TOK + p1] = (gw << 1) | 1;
        g_w[gw * 2 + 1] = e1 / s;
    }
}

// ---------------------------------------------------------------------------
// Grouped GEMM, TF32 wmma, 2-stage register-prefetch pipeline.
// Block tile 128x256, 512 threads (16 warps), warp tile 32x64.
// C[M_e, NDIM] = A[M_e, KDIM] * W_e[NDIM, KDIM]^T
// IS_UP:   A = x rows gathered by token (slot>>1); epilogue bias + exact GELU -> g_h
// !IS_UP:  A = g_h rows by slot;          epilogue bias * router weight  -> g_y
#define BM   128
#define BLKN 256
#define BK   16
#define LDT  20                               // 16 + 4 pad floats per row
#define STAGE_FLOATS ((BM + BLKN) * LDT)      // 7680 floats = 30720 B per stage
#define SMEM_DYN (2 * STAGE_FLOATS * 4)       // 61440 B

template <int NDIM, int KDIM, bool IS_UP>
__global__ __launch_bounds__(512, 1)
void moe_gemm(const float* __restrict__ A0, const float* __restrict__ Wg,
              const float* __restrict__ bias) {
    extern __shared__ float dsm[];            // 2 pipeline stages; epilogue scratch overlay
    __shared__ int srow[BM];

    const int e   = blockIdx.z;
    const int cnt = g_count[e];
    const int m0  = blockIdx.y * BM;
    if (m0 >= cnt) return;
    const int n0  = blockIdx.x * BLKN;
    const int tid = threadIdx.x;
    const int warp = tid >> 5;
    const int lane = tid & 31;

    if (tid < BM) {
        int r = m0 + tid;
        srow[tid] = (r < cnt) ? g_list[e * T_TOK + r] : -1;
    }
    __syncthreads();

    const float* W = Wg + (size_t)e * NDIM * KDIM;

    // ---- loop-invariant staging geometry --------------------------------
    // A tile: 128 rows x 16 cols = 512 float4; exactly 1 per thread.
    const int rA  = tid >> 2;
    const int cA4 = tid & 3;
    int slotA = srow[rA];
    const float* aptr = (slotA < 0) ? nullptr
        : (IS_UP ? (A0 + (size_t)(slotA >> 1) * KDIM + cA4 * 4)
                 : (&g_h[0] + (size_t)slotA * KDIM + cA4 * 4));
    const int offA = rA * LDT + cA4 * 4;

    // B tile: 256 rows x 16 cols = 1024 float4; 2 per thread.
    const float* bptr[2];
    int          offB[2];
#pragma unroll
    for (int it = 0; it < 2; it++) {
        int f4 = tid + it * 512;
        int r  = f4 >> 2;
        int c4 = f4 & 3;
        bptr[it] = W + (size_t)(n0 + r) * KDIM + c4 * 4;
        offB[it] = (BM + r) * LDT + c4 * 4;
    }

    float4 ra, rb[2];
    auto LOAD = [&](int k0) {
        ra = aptr ? *reinterpret_cast<const float4*>(aptr + k0)
                  : make_float4(0.f, 0.f, 0.f, 0.f);
#pragma unroll
        for (int it = 0; it < 2; it++)
            rb[it] = *reinterpret_cast<const float4*>(bptr[it] + k0);
    };
    auto STORE = [&](float* base) {
        float* d = base + offA;
        d[0] = wmma::__float_to_tf32(ra.x);
        d[1] = wmma::__float_to_tf32(ra.y);
        d[2] = wmma::__float_to_tf32(ra.z);
        d[3] = wmma::__float_to_tf32(ra.w);
#pragma unroll
        for (int it = 0; it < 2; it++) {
            float* db = base + offB[it];
            db[0] = wmma::__float_to_tf32(rb[it].x);
            db[1] = wmma::__float_to_tf32(rb[it].y);
            db[2] = wmma::__float_to_tf32(rb[it].z);
            db[3] = wmma::__float_to_tf32(rb[it].w);
        }
    };

    // Warp tile: 32 rows x 64 cols.  4x4 warp grid over 128x256.
    const int wm = warp & 3;      // 0..3 -> 32-row slab
    const int wn = warp >> 2;     // 0..3 -> 64-col slab

    wmma::fragment<wmma::accumulator, 16, 16, 8, float> fc[2][4];
#pragma unroll
    for (int i = 0; i < 2; i++)
#pragma unroll
        for (int j = 0; j < 4; j++) wmma::fill_fragment(fc[i][j], 0.f);

    float* buf[2] = { dsm, dsm + STAGE_FLOATS };
    constexpr int KT = KDIM / BK;

    // Prologue: fill stage 0
    LOAD(0);
    STORE(buf[0]);
    __syncthreads();

    for (int kt = 0; kt < KT; kt++) {
        // Prefetch next k-tile into registers (latency covered by mma below)
        if (kt + 1 < KT) LOAD((kt + 1) * BK);

        const float* sA = buf[kt & 1];
        const float* sB = buf[kt & 1] + BM * LDT;
#pragma unroll
        for (int kk = 0; kk < BK; kk += 8) {
            wmma::fragment<wmma::matrix_a, 16, 16, 8, wmma::precision::tf32,
                           wmma::row_major> fa[2];
            wmma::fragment<wmma::matrix_b, 16, 16, 8, wmma::precision::tf32,
                           wmma::col_major> fb[4];
#pragma unroll
            for (int i = 0; i < 2; i++)
                wmma::load_matrix_sync(fa[i], sA + (wm * 32 + i * 16) * LDT + kk, LDT);
#pragma unroll
            for (int j = 0; j < 4; j++)
                wmma::load_matrix_sync(fb[j], sB + (wn * 64 + j * 16) * LDT + kk, LDT);
#pragma unroll
            for (int i = 0; i < 2; i++)
#pragma unroll
                for (int j = 0; j < 4; j++)
                    wmma::mma_sync(fc[i][j], fa[i], fb[j], fc[i][j]);
        }

        // Refill the other stage (last consumed before previous barrier)
        if (kt + 1 < KT) STORE(buf[(kt + 1) & 1]);
        __syncthreads();
    }

    // ---- epilogue: per-warp private scratch, one 16x16 fragment at a time.
    // scratch = 16 rows x 20 floats (1.28 KB) per warp, overlaid on dsm.
    float* scratch = dsm + warp * (16 * LDT);
    const int rbase = lane >> 4;        // 0 or 1
    const int c     = lane & 15;

#pragma unroll
    for (int i = 0; i < 2; i++) {
#pragma unroll
        for (int j = 0; j < 4; j++) {
            wmma::store_matrix_sync(scratch, fc[i][j], LDT, wmma::mem_row_major);
            __syncwarp();
            const int colg = n0 + wn * 64 + j * 16 + c;
            const float bval = bias[(size_t)e * NDIM + colg];
#pragma unroll
            for (int rr = 0; rr < 8; rr++) {
                int rl   = rr * 2 + rbase;
                int row  = wm * 32 + i * 16 + rl;
                int slot = srow[row];
                if (slot < 0) continue;
                float v = scratch[rl * LDT + c] + bval;
                if (IS_UP) {
                    v = 0.5f * v * (1.f + erff(v * 0.70710678118654752f));
                    g_h[(size_t)slot * UDIM + colg] = v;
                } else {
                    g_y[(size_t)slot * DDIM + colg] = v * g_w[slot];
                }
            }
            __syncwarp();
        }
    }
}

// ---------------------------------------------------------------------------
// out[t,d] = y[slot=2t] + y[slot=2t+1]   (fixed order -> deterministic)
__global__ void combine_kernel(float* __restrict__ out) {
    int i = blockIdx.x * blockDim.x + threadIdx.x;
    if (i >= T_TOK * DDIM) return;
    int t = i >> 10;          // DDIM = 1024
    int d = i & (DDIM - 1);
    out[i] = g_y[(size_t)(2 * t) * DDIM + d] +
             g_y[(size_t)(2 * t + 1) * DDIM + d];
}

// ---------------------------------------------------------------------------
extern "C" void kernel_launch(void* const* d_in, const int* in_sizes, int n_in,
                              void* d_out, int out_size) {
    const float* x  = (const float*)d_in[0];
    const float* wr = (const float*)d_in[1];
    const float* wu = (const float*)d_in[2];
    const float* bu = (const float*)d_in[3];
    const float* wd = (const float*)d_in[4];
    const float* bd = (const float*)d_in[5];
    float* out = (float*)d_out;

    cudaFuncSetAttribute(moe_gemm<UDIM, DDIM, true>,
                         cudaFuncAttributeMaxDynamicSharedMemorySize, SMEM_DYN);
    cudaFuncSetAttribute(moe_gemm<DDIM, UDIM, false>,
                         cudaFuncAttributeMaxDynamicSharedMemorySize, SMEM_DYN);

    init_kernel<<<1, 32>>>();
    router_kernel<<<(T_TOK * 32) / 256, 256>>>(x, wr);

    dim3 gu(UDIM / BLKN, T_TOK / BM, NEXP);   // (16, 32, 8)
    moe_gemm<UDIM, DDIM, true><<<gu, 512, SMEM_DYN>>>(x, wu, bu);

    dim3 gd(DDIM / BLKN, T_TOK / BM, NEXP);   // (4, 32, 8)
    moe_gemm<DDIM, UDIM, false><<<gd, 512, SMEM_DYN>>>(x, wd, bd);

    combine_kernel<<<(T_TOK * DDIM + 255) / 256, 256>>>(out);
}